// round 14
// baseline (speedup 1.0000x reference)
#include <cuda_runtime.h>
typedef unsigned long long ull;

#define OFF_A  49536              // A2: 2 groups x 3088 floats ([193 kp][16])
#define OFF_G  55712              // G:  2 groups x 512 ([64 rows][8])
#define OFF_WL 56736              // 386
#define OFF_MB 57122              // 16 mbarriers (2 groups x 8)
#define OFF_ST 57156              // staging: 2 groups x 3 x 128
#define SMEM_FLOATS 57924
#define SMEM_BYTES (SMEM_FLOATS*4)   // 231696 B

__device__ __forceinline__ void fma2(ull& a, ull b, ull c) {
    asm("fma.rn.f32x2 %0, %1, %2, %0;" : "+l"(a) : "l"(b), "l"(c));
}
__device__ __forceinline__ float hadd2(ull u, ull v) {
    ull s; asm("add.rn.f32x2 %0, %1, %2;" : "=l"(s) : "l"(u), "l"(v));
    float lo, hi; asm("mov.b64 {%0,%1}, %2;" : "=f"(lo), "=f"(hi) : "l"(s));
    return lo + hi;
}
__device__ __forceinline__ float tha(float x) {
    float y; asm("tanh.approx.f32 %0, %1;" : "=f"(y) : "f"(x)); return y;
}
__device__ __forceinline__ unsigned mapa_(unsigned a, int r) {
    unsigned ra; asm("mapa.shared::cluster.u32 %0, %1, %2;" : "=r"(ra) : "r"(a), "r"(r));
    return ra;
}
__device__ __forceinline__ void mbinit(unsigned a, unsigned n) {
    asm volatile("mbarrier.init.shared.b64 [%0], %1;" :: "r"(a), "r"(n) : "memory");
}
__device__ __forceinline__ void exptx(unsigned a, unsigned n) {
    asm volatile("mbarrier.arrive.expect_tx.shared.b64 _, [%0], %1;" :: "r"(a), "r"(n) : "memory");
}
__device__ __forceinline__ void rarr(unsigned a, int r) {
    unsigned ra = mapa_(a, r);
    asm volatile("mbarrier.arrive.release.cluster.shared::cluster.b64 _, [%0];" :: "r"(ra) : "memory");
}
__device__ __forceinline__ void sta(unsigned d, unsigned m, float v) {
    asm volatile("st.async.shared::cluster.mbarrier::complete_tx::bytes.b32 [%0], %1, [%2];"
                 :: "r"(d), "r"(__float_as_uint(v)), "r"(m) : "memory");
}
__device__ __forceinline__ void blkcp(unsigned dst, unsigned src, unsigned mb) {
    asm volatile("cp.async.bulk.shared::cluster.shared::cta.mbarrier::complete_tx::bytes [%0], [%1], %2, [%3];"
                 :: "r"(dst), "r"(src), "r"(512u), "r"(mb) : "memory");
}
__device__ __forceinline__ void waitp(unsigned a, unsigned p) {
    unsigned d;
    asm volatile("{\n.reg .pred P;\nmbarrier.try_wait.parity.acquire.cluster.shared::cta.b64 P,[%1],%2;\nselp.b32 %0,1,0,P;\n}"
                 : "=r"(d) : "r"(a), "r"(p) : "memory");
    while (!d)
        asm volatile("{\n.reg .pred P;\nmbarrier.try_wait.parity.acquire.cluster.shared::cta.b64 P,[%1],%2,0x989680;\nselp.b32 %0,1,0,P;\n}"
                     : "=r"(d) : "r"(a), "r"(p) : "memory");
}
// full-K segment: lane = 1 row x 2 batches; 4 rotating f32x2 accumulators
__device__ __forceinline__ void segF(const ull* __restrict__ Wseg, const ull* __restrict__ Aseg,
                                     int wr, int bp2, ull* acc) {
    #pragma unroll 8
    for (int kp = 0; kp < 64; kp++) {
        ull w2 = Wseg[(kp << 6) + wr];
        ulonglong2 q = *(const ulonglong2*)(Aseg + (kp << 3) + bp2);
        fma2(acc[(kp & 1)],     w2, q.x);
        fma2(acc[2 + (kp & 1)], w2, q.y);
    }
}

__global__ void __launch_bounds__(512, 1) __cluster_dims__(8, 1, 1)
lstm_k(const float* __restrict__ xg,
       const float* __restrict__ Wih1, const float* __restrict__ Whh1,
       const float* __restrict__ bih1, const float* __restrict__ bhh1,
       const float* __restrict__ Wih2, const float* __restrict__ Whh2,
       const float* __restrict__ bih2, const float* __restrict__ bhh2,
       const float* __restrict__ Wih3, const float* __restrict__ Whh3,
       const float* __restrict__ bih3, const float* __restrict__ bhh3,
       const float* __restrict__ Wlin, const float* __restrict__ blin,
       float* __restrict__ out)
{
    extern __shared__ float sm[];
    float* W  = sm;
    float* WL = sm + OFF_WL;

    const int tid = threadIdx.x;
    unsigned ur; asm("mov.u32 %0, %%cluster_ctarank;" : "=r"(ur));
    const int rank = (int)ur;
    const int b0 = (blockIdx.x >> 3) * 16;
    const unsigned sbase = (unsigned)__cvta_generic_to_shared(sm);

    // ---- one-time weight load (identical layout to prior rounds) ----
    {
        const float* WihA[3] = {Wih1, Wih2, Wih3};
        const float* WhhA[3] = {Whh1, Whh2, Whh3};
        const int KihA[3] = {1, 129, 257};
        const int KPA[3]  = {65, 129, 193};
        const int WOA[3]  = {0, 65*128, 194*128};
        for (int L = 0; L < 3; L++) {
            const int Kih = KihA[L], KP = KPA[L];
            float* Wd = W + WOA[L];
            for (int i = tid; i < KP*128; i += 512) {
                int wkp = i >> 7, r = i & 127, l = r >> 1, par = r & 1;
                int grow = ((l >> 4) << 7) + (rank << 4) + (l & 15);
                float v;
                if (wkp < 64)        v = WhhA[L][grow*128 + 2*wkp + par];
                else if (wkp == 64)  v = par ? 0.0f : WihA[L][grow*Kih];
                else                 v = WihA[L][grow*Kih + 1 + 2*(wkp - 65) + par];
                if ((l >> 4) != 2) v *= 0.5f;
                Wd[i] = v;
            }
        }
        for (int i = tid; i < 384; i += 512) WL[i] = Wlin[i + 1];
        if (tid == 0) { WL[384] = Wlin[0]; WL[385] = blin[0]; }
        for (int i = tid; i < 6176; i += 512) sm[OFF_A + i] = 0.0f;
        if (tid == 0)
            for (int gg = 0; gg < 2; gg++) {
                unsigned mb = sbase + (OFF_MB + gg*16)*4;
                mbinit(mb + 0, 8);  mbinit(mb + 8, 8);  mbinit(mb + 16, 8);  // e1 e2 e3
                mbinit(mb + 24, 1); mbinit(mb + 32, 1); mbinit(mb + 40, 1);  // f1 f2 f3
                mbinit(mb + 48, 1); mbinit(mb + 56, 8);                      // fx ex
            }
    }
    __syncthreads();
    asm volatile("barrier.cluster.arrive.aligned;" ::: "memory");
    asm volatile("barrier.cluster.wait.aligned;" ::: "memory");

    // ---- group setup ----
    const int g    = tid >> 8;
    const int gtid = tid & 255;
    const int gw   = gtid >> 5;
    const int lane = tid & 31;
    const int wr   = (gw << 3) + (lane >> 2);   // gate row 0..63
    const int bp2  = (lane & 3) << 1;           // batch pair base (ull idx)
    float* A2g = sm + OFF_A + g*3088;
    const ull* A2u = (const ull*)A2g;
    float* Gg  = sm + OFF_G + g*512;
    float* STg = sm + OFF_ST + g*384;
    const ull* Wul = (const ull*)W;

    const unsigned mbg = sbase + (OFF_MB + g*16)*4;
    const unsigned e1 = mbg, e2 = mbg + 8, e3 = mbg + 16;
    const unsigned f1 = mbg + 24, f2 = mbg + 32, f3 = mbg + 40;
    const unsigned fx = mbg + 48, ex = mbg + 56;
    const unsigned abg = sbase + (OFF_A + g*3088)*4;
    unsigned rb[8];
    #pragma unroll
    for (int r = 0; r < 8; r++) rb[r] = mapa_(abg, r);

    // epilogue biases (pre-scaled): cell = (row j, batch b)
    const int ej = (gtid >> 3) & 15, eb = gtid & 7;
    float bR[3][4];
    {
        const float* bihA[3] = {bih1, bih2, bih3};
        const float* bhhA[3] = {bhh1, bhh2, bhh3};
        #pragma unroll
        for (int L = 0; L < 3; L++)
            #pragma unroll
            for (int q = 0; q < 4; q++) {
                int grow = (q << 7) + (rank << 4) + ej;
                float b = bihA[L][grow] + bhhA[L][grow];
                bR[L][q] = (q == 2) ? b : 0.5f * b;
            }
    }
    float cst[3] = {0.f, 0.f, 0.f};
    float xn = (gtid < 8) ? xg[(b0 + 8*g + gtid)*1024] : 0.0f;
    unsigned phx = 0;
    const int hb = rank;                         // head batch (local)

#define GBAR() asm volatile("bar.sync %0, 256;" :: "r"(g + 1) : "memory")

#define LAYER(Lc, eL, fL, WUOFF, PRE) do {                                    \
    const ull* Wu = Wul + WUOFF;                                              \
    if (t) waitp(fL, pp);                   /* recurrent h_L(t-1) arrived */  \
    if (gtid == 0) exptx(fL, 4096);         /* fresh phase */                 \
    ull acc[4] = {0,0,0,0};                                                   \
    segF(Wu, A2u + (Lc << 9), wr, bp2, acc);            /* rec h_L */         \
    {                                                    /* x (1 kp) */       \
        ull w2 = Wu[4096 + wr];                                               \
        ulonglong2 q = *(const ulonglong2*)(A2u + 1536 + bp2);                \
        fma2(acc[0], w2, q.x); fma2(acc[2], w2, q.y);                         \
    }                                                                         \
    GBAR();                                 /* early reads done group-wide */ \
    if (gtid < 8) rarr(eL, gtid);                                             \
    PRE                                                                       \
    *(float2*)(Gg + wr*8 + bp2) =                                             \
        make_float2(hadd2(acc[0], acc[1]), hadd2(acc[2], acc[3]));            \
    GBAR();                                 /* G visible */                   \
    if (gtid < 128) {                       /* epilogue: 1 cell/thread */     \
        const float bi = bR[Lc][0], bf = bR[Lc][1];                           \
        const float bg = bR[Lc][2], bo = bR[Lc][3];                           \
        float ii = fmaf(0.5f, tha(Gg[ej*8 + eb] + bi), 0.5f);                 \
        float ff = fmaf(0.5f, tha(Gg[(16+ej)*8 + eb] + bf), 0.5f);            \
        float gv = tha(Gg[(32+ej)*8 + eb] + bg);                              \
        float oo = fmaf(0.5f, tha(Gg[(48+ej)*8 + eb] + bo), 0.5f);            \
        float c = ff*cst[Lc] + ii*gv; cst[Lc] = c;                            \
        float h = oo*tha(c);                                                  \
        waitp(eL, pc);                      /* prev staging fully read */     \
        STg[Lc*128 + (ej >> 1)*16 + 2*eb + (ej & 1)] = h;                     \
    }                                                                         \
    GBAR();                                 /* staging + G reads done */      \
    if (gtid == 0) {                                                          \
        asm volatile("fence.proxy.async.shared::cta;" ::: "memory");          \
        unsigned src = sbase + (OFF_ST + g*384 + Lc*128)*4u;                  \
        unsigned dof = (unsigned)(Lc*4096 + rank*512);                        \
        _Pragma("unroll")                                                     \
        for (int r = 0; r < 8; r++)                                           \
            blkcp(mapa_(abg + dof, r), src, mapa_(fL, r));                    \
    }                                                                         \
} while (0)

    for (int t = 0; t < 1056; t++) {
        const unsigned pc = t & 1, pp = (t - 1) & 1;
        if (t < 1024 && gtid < 8) A2g[3072 + 2*gtid] = xn;   // teacher x
        GBAR();
        if (gtid < 8 && t + 1 < 1024) xn = xg[(b0 + 8*g + gtid)*1024 + t + 1];
        if (t >= 1024) { waitp(fx, phx); phx ^= 1; }
        if (gtid == 0 && t >= 1023 && t < 1055) exptx(fx, 32);

        LAYER(0, e1, f1, 0, );
        LAYER(1, e2, f2, 4160,
              waitp(f1, pc);
              segF(Wu + 4160, A2u, wr, bp2, acc); );
        LAYER(2, e3, f3, 12416,
              waitp(f1, pc);
              segF(Wu + 4160, A2u, wr, bp2, acc);
              waitp(f2, pc);
              segF(Wu + 8256, A2u + 512, wr, bp2, acc); );

        // head: this CTA's group handles local batch = rank
        float o = 0.f;
        if (gtid < 32) {
            waitp(f3, pc);
            float s = 0.f;
            for (int sl = lane; sl < 385; sl += 32)
                s += A2g[(sl >> 1)*16 + 2*hb + (sl & 1)] * WL[sl];
            #pragma unroll
            for (int off = 16; off; off >>= 1) s += __shfl_xor_sync(0xffffffffu, s, off);
            if (lane == 0) {
                o = s + WL[385];
                out[(b0 + 8*g + hb)*1056 + t] = o;
            }
        }
        GBAR();                                // all x(t)/A2 reads done
        if (gtid < 8) rarr(ex, gtid);
        if (t >= 1023 && t < 1055 && gtid == 0) {
            waitp(ex, pc);                     // x slot free everywhere
            const unsigned ox = (unsigned)(3072 + 2*hb) << 2;
            #pragma unroll
            for (int r = 0; r < 8; r++) sta(rb[r] + ox, mapa_(fx, r), o);
        }
        GBAR();
    }

    if (gtid == 0) { waitp(f1, 1); waitp(f2, 1); waitp(f3, 1); }
    __syncthreads();
    asm volatile("barrier.cluster.arrive.aligned;" ::: "memory");
    asm volatile("barrier.cluster.wait.aligned;" ::: "memory");
}

extern "C" void kernel_launch(void* const* d_in, const int* in_sizes, int n_in,
                              void* d_out, int out_size) {
    cudaFuncSetAttribute(lstm_k, cudaFuncAttributeMaxDynamicSharedMemorySize, SMEM_BYTES);
    lstm_k<<<128, 512, SMEM_BYTES>>>(
        (const float*)d_in[0],
        (const float*)d_in[1], (const float*)d_in[2],
        (const float*)d_in[3], (const float*)d_in[4],
        (const float*)d_in[5], (const float*)d_in[6],
        (const float*)d_in[7], (const float*)d_in[8],
        (const float*)d_in[9], (const float*)d_in[10],
        (const float*)d_in[11], (const float*)d_in[12],
        (const float*)d_in[13], (const float*)d_in[14],
        (float*)d_out);
}

// round 16
// speedup vs baseline: 1.1260x; 1.1260x over previous
#include <cuda_runtime.h>
typedef unsigned long long ull;

#define OFF_A  49152              // A2: 3 x 2048 floats (h1,h2,h3) [64kp][32]
#define OFF_GA 55296              // 64x16
#define OFF_GB 56320              // 64x16
#define OFF_WL 57344              // 386
#define OFF_XR 57732              // 4 x 16 ring
#define OFF_MB 57800              // 7 mbarriers
#define SMEM_FLOATS 57824
#define SMEM_BYTES (SMEM_FLOATS*4)

__device__ __forceinline__ void fma2(ull& a, ull b, ull c) {
    asm("fma.rn.f32x2 %0, %1, %2, %0;" : "+l"(a) : "l"(b), "l"(c));
}
__device__ __forceinline__ float hadd(ull v) {
    float lo, hi; asm("mov.b64 {%0,%1}, %2;" : "=f"(lo), "=f"(hi) : "l"(v));
    return lo + hi;
}
__device__ __forceinline__ float tha(float x) {
    float y; asm("tanh.approx.f32 %0, %1;" : "=f"(y) : "f"(x)); return y;
}
__device__ __forceinline__ unsigned mapa_(unsigned a, int r) {
    unsigned ra; asm("mapa.shared::cluster.u32 %0, %1, %2;" : "=r"(ra) : "r"(a), "r"(r));
    return ra;
}
__device__ __forceinline__ void mbinit(unsigned a, unsigned n) {
    asm volatile("mbarrier.init.shared.b64 [%0], %1;" :: "r"(a), "r"(n) : "memory");
}
__device__ __forceinline__ void exptx(unsigned a, unsigned n) {
    asm volatile("mbarrier.arrive.expect_tx.shared.b64 _, [%0], %1;" :: "r"(a), "r"(n) : "memory");
}
__device__ __forceinline__ void rarr(unsigned a, int r) {
    unsigned ra = mapa_(a, r);
    asm volatile("mbarrier.arrive.release.cluster.shared::cluster.b64 _, [%0];" :: "r"(ra) : "memory");
}
__device__ __forceinline__ void larr(unsigned a) {   // local release-arrive
    asm volatile("mbarrier.arrive.shared.b64 _, [%0];" :: "r"(a) : "memory");
}
__device__ __forceinline__ void sta(unsigned d, unsigned m, float v) {
    asm volatile("st.async.shared::cluster.mbarrier::complete_tx::bytes.b32 [%0], %1, [%2];"
                 :: "r"(d), "r"(__float_as_uint(v)), "r"(m) : "memory");
}
__device__ __forceinline__ void blkcp(unsigned dst, unsigned src, unsigned mb) {
    asm volatile("cp.async.bulk.shared::cluster.shared::cta.mbarrier::complete_tx::bytes [%0], [%1], %2, [%3];"
                 :: "r"(dst), "r"(src), "r"(1024u), "r"(mb) : "memory");
}
__device__ __forceinline__ void waitp(unsigned a, unsigned p) {
    unsigned d;
    asm volatile("{\n.reg .pred P;\nmbarrier.try_wait.parity.acquire.cluster.shared::cta.b64 P,[%1],%2;\nselp.b32 %0,1,0,P;\n}"
                 : "=r"(d) : "r"(a), "r"(p) : "memory");
    while (!d)
        asm volatile("{\n.reg .pred P;\nmbarrier.try_wait.parity.acquire.cluster.shared::cta.b64 P,[%1],%2,0x989680;\nselp.b32 %0,1,0,P;\n}"
                     : "=r"(d) : "r"(a), "r"(p) : "memory");
}
// 64-kp segment: warp-private rows, lane = 1 row x 4 batches
__device__ __forceinline__ void segW(const ull* __restrict__ Wb, const ull* __restrict__ Ab,
                                     int row, int b4, ull* acc) {
    #pragma unroll 8
    for (int kp = 0; kp < 64; kp++) {
        ull w2 = Wb[(kp << 6) + row];
        ulonglong2 q0 = *(const ulonglong2*)(Ab + (kp << 4) + b4);
        ulonglong2 q1 = *(const ulonglong2*)(Ab + (kp << 4) + b4 + 2);
        fma2(acc[0], w2, q0.x); fma2(acc[1], w2, q0.y);
        fma2(acc[2], w2, q1.x); fma2(acc[3], w2, q1.y);
    }
}

__global__ void __launch_bounds__(512, 1) __cluster_dims__(8, 1, 1)
lstm_k(const float* __restrict__ xg,
       const float* __restrict__ Wih1, const float* __restrict__ Whh1,
       const float* __restrict__ bih1, const float* __restrict__ bhh1,
       const float* __restrict__ Wih2, const float* __restrict__ Whh2,
       const float* __restrict__ bih2, const float* __restrict__ bhh2,
       const float* __restrict__ Wih3, const float* __restrict__ Whh3,
       const float* __restrict__ bih3, const float* __restrict__ bhh3,
       const float* __restrict__ Wlin, const float* __restrict__ blin,
       float* __restrict__ out)
{
    extern __shared__ float sm[];
    float* W   = sm;
    float* A2f = sm + OFF_A;
    float* WL  = sm + OFF_WL;
    float* XR  = sm + OFF_XR;

    const int tid = threadIdx.x;
    unsigned ur; asm("mov.u32 %0, %%cluster_ctarank;" : "=r"(ur));
    const int rank = (int)ur;
    const int b0 = (blockIdx.x >> 3) * 16;
    const unsigned sbase = (unsigned)__cvta_generic_to_shared(sm);
    const unsigned e1 = sbase + (OFF_MB + 0)*4, e2 = sbase + (OFF_MB + 2)*4;
    const unsigned e3 = sbase + (OFF_MB + 4)*4;
    const unsigned f1 = sbase + (OFF_MB + 6)*4, f2 = sbase + (OFF_MB + 8)*4;
    const unsigned f3 = sbase + (OFF_MB + 10)*4, fx = sbase + (OFF_MB + 12)*4;

    {   // one-time weight load: [kp][64 rows][2 kpar]; i,f,o rows pre-scaled 0.5; no x col
        const float* Wh[3] = {Whh1, Whh2, Whh3};
        const int KP[3] = {64, 128, 192};
        const int WB[3] = {0, 8192, 24576};
        for (int L = 0; L < 3; L++) {
            float* Wd = W + WB[L];
            for (int i = tid; i < KP[L]*128; i += 512) {
                int wkp = i >> 7, r = i & 127, l = r >> 1, par = r & 1;
                int grow = ((l >> 4) << 7) + (rank << 4) + (l & 15);
                float v;
                if (wkp < 64)      v = Wh[L][grow*128 + 2*wkp + par];
                else if (L == 1)   v = Wih2[grow*129 + 1 + 2*(wkp - 64) + par];
                else               v = (wkp < 128) ? Wih3[grow*257 + 1 + 2*(wkp - 64) + par]
                                                   : Wih3[grow*257 + 129 + 2*(wkp - 128) + par];
                if ((l >> 4) != 2) v *= 0.5f;
                Wd[i] = v;
            }
        }
        for (int i = tid; i < 384; i += 512) WL[i] = Wlin[i + 1];
        if (tid == 0) { WL[384] = Wlin[0]; WL[385] = blin[0]; }
        for (int i = tid; i < 6144; i += 512) A2f[i] = 0.0f;
        if (tid < 16) { XR[tid] = xg[(b0 + tid)*1024]; XR[16 + tid] = xg[(b0 + tid)*1024 + 1]; }
        if (tid == 0) {
            mbinit(e1, 32); mbinit(e2, 24); mbinit(e3, 16);
            mbinit(f1, 2); mbinit(f2, 2); mbinit(f3, 1); mbinit(fx, 1);
        }
    }
    __syncthreads();
    asm volatile("barrier.cluster.arrive.aligned;" ::: "memory");
    asm volatile("barrier.cluster.wait.aligned;" ::: "memory");
    if (tid < 8) {   // prime t=-1 reader classes
        rarr(e1, tid); rarr(e1, tid); rarr(e1, tid);
        rarr(e2, tid); rarr(e2, tid);
        rarr(e3, tid);
    }

    const int grp  = tid >> 8;             // 0 = A (L1,L2), 1 = B (L3,head)
    const int gtid = tid & 255;
    const int lane = tid & 31;
    const int row  = (((tid >> 5) & 7) << 3) + (lane >> 2);  // gate row 0..63
    const int b4   = (lane & 3) << 2;                        // batch quad
    const int ej   = gtid >> 4, eb = gtid & 15;              // epilogue cell
    float* G   = sm + (grp ? OFF_GB : OFF_GA);
    float* Gp  = G + row*16 + b4;
    const ull* Wu  = (const ull*)W;
    const ull* A2u = (const ull*)A2f;
    const unsigned abase = sbase + OFF_A*4;
    // own-slice float offsets (within A2) for epilogue writes
    const int sl1 = (rank*8 + (ej >> 1))*32 + 2*eb + (ej & 1);

    // biases + x-weights in regs (pre-scaled); A:[L1,L2], B:[L3]
    float bs[2][4], wx[2][4];
    {
        #pragma unroll
        for (int q = 0; q < 4; q++) {
            int grow = (q << 7) + (rank << 4) + ej;
            float b1, w1, b2, w2;
            if (grp == 0) {
                b1 = bih1[grow] + bhh1[grow]; w1 = Wih1[grow];
                b2 = bih2[grow] + bhh2[grow]; w2 = Wih2[grow*129];
            } else {
                b1 = bih3[grow] + bhh3[grow]; w1 = Wih3[grow*257];
                b2 = 0.f; w2 = 0.f;
            }
            float s = (q == 2) ? 1.0f : 0.5f;
            bs[0][q] = s*b1; wx[0][q] = s*w1;
            bs[1][q] = s*b2; wx[1][q] = s*w2;
        }
    }

#define GBAR() asm volatile("bar.sync 1, 256;" ::: "memory")
#define BBAR() asm volatile("bar.sync 2, 256;" ::: "memory")
#define EPI(Lidx, cvar, hvar) do {                                            \
    float xi = XR[(t & 3)*16 + eb];                                           \
    float gi = fmaf(0.5f, tha(G[ej*16 + eb]      + bs[Lidx][0] + wx[Lidx][0]*xi), 0.5f); \
    float gf = fmaf(0.5f, tha(G[(16+ej)*16 + eb] + bs[Lidx][1] + wx[Lidx][1]*xi), 0.5f); \
    float gg = tha(G[(32+ej)*16 + eb]            + bs[Lidx][2] + wx[Lidx][2]*xi);        \
    float go = fmaf(0.5f, tha(G[(48+ej)*16 + eb] + bs[Lidx][3] + wx[Lidx][3]*xi), 0.5f); \
    float c = gf*cvar + gi*gg; cvar = c; hvar = go*tha(c);                    \
} while (0)
#define GST() do {                                                            \
    *(float4*)Gp = make_float4(hadd(acc[0]), hadd(acc[1]), hadd(acc[2]), hadd(acc[3])); \
} while (0)
#define BCAST(fL, Lreg) do {                                                  \
    asm volatile("fence.proxy.async.shared::cta;" ::: "memory");              \
    unsigned srcb = abase + (unsigned)((Lreg)*2048 + rank*256)*4u;            \
    _Pragma("unroll")                                                         \
    for (int r = 0; r < 8; r++)                                               \
        if (r != rank) blkcp(mapa_(srcb, r), srcb, mapa_(fL, r));             \
} while (0)

    if (grp == 0) {
        // ===================== GROUP A: L1 + L2 =====================
        float c1 = 0.f, c2 = 0.f, h;
        for (int t = 0; t < 1056; t++) {
            const unsigned pc = t & 1, pp = (t - 1) & 1;
            if (t) { waitp(f1, pp); waitp(f2, pp); }
            if (gtid == 0) { exptx(f1, 7168); exptx(f2, 7168); }
            if (t >= 1024) waitp(fx, (t - 1024) & 1);
            // ---- L1 ----
            {
                ull acc[4] = {0,0,0,0};
                segW(Wu, A2u, row, b4, acc);          // rec h1(t-1)
                GST();
                GBAR();
                if (gtid < 8) rarr(e1, gtid);         // L1rec(t)
                EPI(0, c1, h);
                waitp(e1, pc);                        // all readers of h1(t-1) done
                A2f[sl1] = h;                         // own slice
                GBAR();
                if (gtid == 0) { BCAST(f1, 0); larr(f1); }
            }
            // ---- L2 ----
            {
                ull acc[4] = {0,0,0,0};
                segW(Wu + 4096, A2u + 1024, row, b4, acc);   // rec h2(t-1)
                GBAR();
                if (gtid < 8) rarr(e2, gtid);         // L2rec(t)
                waitp(f1, pc);                        // h1(t) complete
                segW(Wu + 8192, A2u, row, b4, acc);   // h1(t)
                GST();
                GBAR();
                if (gtid < 8) rarr(e1, gtid);         // L2read(t)
                EPI(1, c2, h);
                waitp(e2, pc);
                A2f[2048 + sl1] = h;
                GBAR();
                if (gtid == 0) { BCAST(f2, 1); larr(f2); }
            }
        }
        waitp(f1, 1); waitp(f2, 1);
    } else {
        // ===================== GROUP B: L3 + head =====================
        float c3 = 0.f, h, xn2 = 0.f;
        if (gtid < 16) xn2 = xg[(b0 + gtid)*1024 + 2];
        for (int t = 0; t < 1056; t++) {
            const unsigned pc = t & 1, pp = (t - 1) & 1;
            if (t) waitp(f3, pp);
            if (gtid == 0) exptx(f3, 7168);
            if (t >= 1024) waitp(fx, (t - 1024) & 1);
            if (gtid == 0 && t >= 1023 && t < 1055) exptx(fx, 64);
            ull acc[4] = {0,0,0,0};
            segW(Wu + 12288, A2u + 2048, row, b4, acc);   // rec h3(t-1)
            BBAR();
            if (gtid < 8) rarr(e3, gtid);             // L3rec(t)
            waitp(f1, pc);
            segW(Wu + 16384, A2u, row, b4, acc);      // h1(t)
            BBAR();
            if (gtid < 8) rarr(e1, gtid);             // Bread(t)
            waitp(f2, pc);
            segW(Wu + 20480, A2u + 1024, row, b4, acc); // h2(t)
            GST();
            BBAR();
            if (gtid < 8) rarr(e2, gtid);             // Bh2read(t)
            EPI(0, c3, h);
            waitp(e3, pc);
            A2f[4096 + sl1] = h;
            BBAR();
            if (gtid == 0) BCAST(f3, 2);
            // ---- head ----
            float o = 0.f;
            const int bl = 2*rank + (gtid >> 5);
            if (gtid < 64) {
                waitp(f3, pc);
                float s = 0.f;
                #pragma unroll 4
                for (int sl = lane; sl < 384; sl += 32)
                    s += A2f[(sl >> 7)*2048 + ((sl & 127) >> 1)*32 + 2*bl + ((sl & 127) & 1)]
                         * WL[sl];
                #pragma unroll
                for (int off = 16; off; off >>= 1) s += __shfl_xor_sync(0xffffffffu, s, off);
                if (lane == 0) {
                    o = s + WL[384]*XR[(t & 3)*16 + bl] + WL[385];
                    out[(b0 + bl)*1056 + t] = o;
                }
            }
            BBAR();                                   // head reads done group-wide
            if (gtid < 16 && t <= 1021)               // teacher x(t+2) (before head rarr!)
                XR[((t + 2) & 3)*16 + gtid] = xn2;
            if (gtid < 16 && t + 3 < 1024) xn2 = xg[(b0 + gtid)*1024 + t + 3];
            if (gtid < 8) { rarr(e1, gtid); rarr(e2, gtid); rarr(e3, gtid); }  // head(t)
            if (t >= 1023 && t < 1055 && gtid < 64 && lane == 0) {
                const unsigned ox = sbase + (unsigned)(OFF_XR + ((t + 1) & 3)*16 + bl)*4u;
                #pragma unroll
                for (int r = 0; r < 8; r++) sta(mapa_(ox, r), mapa_(fx, r), o);
            }
        }
        waitp(f3, 1);
    }
    __syncthreads();
    asm volatile("barrier.cluster.arrive.aligned;" ::: "memory");
    asm volatile("barrier.cluster.wait.aligned;" ::: "memory");
}

extern "C" void kernel_launch(void* const* d_in, const int* in_sizes, int n_in,
                              void* d_out, int out_size) {
    cudaFuncSetAttribute(lstm_k, cudaFuncAttributeMaxDynamicSharedMemorySize, SMEM_BYTES);
    lstm_k<<<128, 512, SMEM_BYTES>>>(
        (const float*)d_in[0],
        (const float*)d_in[1], (const float*)d_in[2],
        (const float*)d_in[3], (const float*)d_in[4],
        (const float*)d_in[5], (const float*)d_in[6],
        (const float*)d_in[7], (const float*)d_in[8],
        (const float*)d_in[9], (const float*)d_in[10],
        (const float*)d_in[11], (const float*)d_in[12],
        (const float*)d_in[13], (const float*)d_in[14],
        (float*)d_out);
}